// round 14
// baseline (speedup 1.0000x reference)
#include <cuda_runtime.h>
#include <cuda_fp16.h>
#include <cstdint>

#define NROW 4096
#define DDIM 512
#define CCAP 128   // max members per class (mean 64, sd ~8)

// -------------------------- device scratch (no allocs) ----------------------
__device__ float g_sq[NROW];
__device__ float g_rowmax[NROW];   // max_distance per row (atomicMax, reset each call)
__device__ float g_negmin[NROW];   // min dist over diff-label j (atomicMin)
__device__ float g_part[64];       // per-class partial sums of (posmax + pen)
__device__ int   g_clist[64 * CCAP];  // per-class member lists (ordered)
__device__ int   g_ccnt[64];
__device__ int   g_rank[NROW];        // rank of row within its class list
__device__ int   g_done;              // completion counter for fused final reduce
__device__ float g_cd[(size_t)NROW * CCAP];  // compact same-class distances (2 MB)
__device__ __half g_h[(size_t)NROW * DDIM];  // fp16 features

// -------------------------- PTX helpers -------------------------------------
__device__ __forceinline__ uint32_t smem_u32(const void* p) {
    uint32_t a;
    asm("{ .reg .u64 t; cvta.to.shared.u64 t, %1; cvt.u32.u64 %0, t; }" : "=r"(a) : "l"(p));
    return a;
}

#define CP_ASYNC16(dst, src) \
    asm volatile("cp.async.cg.shared.global [%0], [%1], 16;" :: "r"(dst), "l"(src) : "memory")
#define CP_COMMIT() asm volatile("cp.async.commit_group;" ::: "memory")
#define CP_WAIT(n)  asm volatile("cp.async.wait_group %0;" :: "n"(n) : "memory")

#define LDSM_X4(R, addr) \
    asm volatile("ldmatrix.sync.aligned.m8n8.x4.shared.b16 {%0,%1,%2,%3}, [%4];" \
        : "=r"((R)[0]), "=r"((R)[1]), "=r"((R)[2]), "=r"((R)[3]) : "r"(addr))

// D(16x8,f16) += A(16x16 f16, row) * B(16x8 f16, col: B[n][k]) — fp16 accumulator
__device__ __forceinline__ void mma_f16acc(uint32_t* d, const uint32_t* a, uint32_t b0, uint32_t b1) {
    asm volatile(
        "mma.sync.aligned.m16n8k16.row.col.f16.f16.f16.f16 "
        "{%0,%1}, {%2,%3,%4,%5}, {%6,%7}, {%0,%1};"
        : "+r"(d[0]), "+r"(d[1])
        : "r"(a[0]), "r"(a[1]), "r"(a[2]), "r"(a[3]), "r"(b0), "r"(b1));
}

// -------------------------- dist kernel SMEM layout -------------------------
#define SM_SQI   0
#define SM_SQJ   512
#define SM_LABI  1024
#define SM_LABJ  1536
#define SM_RNKI  2048
#define SM_RNKJ  2560
#define SM_BUF   3072
#define ROWB     80                // bytes per smem tile row (32 halves + 8 pad)
#define TILEB    (128 * ROWB)      // 10240
#define STAGE_BYTES (2 * TILEB)    // 20480  (A tile + B tile)
#define NSTAGE   4
#define SMEM_TOTAL (SM_BUF + NSTAGE * STAGE_BYTES)   // 84992 > 3072 + 66048 (sd reuse)

// ---------------------------------------------------------------------------
// Kernel A: fused prep — conv (blocks 0..2047) + classlist (blocks 2048..2111)
// ---------------------------------------------------------------------------
__global__ void prep_kernel(const float* __restrict__ X, const int* __restrict__ lab) {
    if (blockIdx.x < NROW / 2) {
        // ---- conv: fp16 convert + squared norms + stat reset (2 rows/block)
        int row = blockIdx.x * 2 + (threadIdx.x >> 7);
        int t = threadIdx.x & 127;     // 0..127, one float4 each
        const float4* xr = reinterpret_cast<const float4*>(X + (size_t)row * DDIM);
        float4 v = xr[t];
        float vv[4] = {v.x, v.y, v.z, v.w};
        float s = 0.f;
        __half h[4];
        #pragma unroll
        for (int k = 0; k < 4; k++) { s += vv[k] * vv[k]; h[k] = __float2half_rn(vv[k]); }
        *reinterpret_cast<uint2*>(g_h + (size_t)row * DDIM + t * 4) = *reinterpret_cast<uint2*>(h);
        #pragma unroll
        for (int q = 16; q > 0; q >>= 1) s += __shfl_xor_sync(0xffffffffu, s, q);
        __shared__ float ws[8];
        if ((threadIdx.x & 31) == 0) ws[threadIdx.x >> 5] = s;
        __syncthreads();
        if (t == 0) {
            int w0 = (threadIdx.x >> 7) * 4;
            g_sq[row] = ws[w0] + ws[w0 + 1] + ws[w0 + 2] + ws[w0 + 3];
            g_rowmax[row] = 0.f;
            g_negmin[row] = 3.4028235e38f;
        }
    } else {
        // ---- classlist: warp 0 builds ordered member list for class c
        int c = blockIdx.x - NROW / 2;
        if (threadIdx.x == 32 && c == 0) g_done = 0;   // reset final counter
        if (threadIdx.x < 32) {
            int lane = threadIdx.x;
            int cnt = 0;
            for (int base = 0; base < NROW; base += 32) {
                bool m = (lab[base + lane] == c);
                unsigned bal = __ballot_sync(0xffffffffu, m);
                if (m) {
                    int pos = cnt + __popc(bal & ((1u << lane) - 1u));
                    if (pos < CCAP) {
                        g_clist[c * CCAP + pos] = base + lane;
                        g_rank[base + lane] = pos;
                    }
                }
                cnt += __popc(bal);
            }
            if (lane == 0) g_ccnt[c] = cnt < CCAP ? cnt : CCAP;
        }
    }
}

// ---------------------------------------------------------------------------
// Kernel B: fp16 mma.sync (fp16 accum) Gram -> stats + compact same-class dists
//   528 upper-triangle tiles, 16 K-chunks of 32, 4-stage pipeline, 1 sync/chunk
// ---------------------------------------------------------------------------
__device__ __forceinline__ void load_chunk(uint32_t stage_base, int m0, int n0, int k0, int tid) {
    #pragma unroll
    for (int t = 0; t < 2; t++) {        // 0 = A rows (m0), 1 = B rows (n0)
        int r0 = t ? n0 : m0;
        uint32_t dbase = stage_base + t * TILEB;
        #pragma unroll
        for (int q = 0; q < 2; q++) {
            int idx = q * 256 + tid;     // 0..511
            int row = idx >> 2;
            int seg = idx & 3;           // 4 x 16B = 32 halves per row
            const __half* gs = g_h + (size_t)(r0 + row) * DDIM + k0 + seg * 8;
            CP_ASYNC16(dbase + (uint32_t)(row * ROWB + seg * 16), gs);
        }
    }
    CP_COMMIT();
}

__global__ __launch_bounds__(256, 2) void dist_kernel(const int* __restrict__ lab) {
    // decode linear tile index -> (bi, bj) with bi <= bj over 32x32 triangle
    const int t0 = (int)blockIdx.x;
    int bi = (int)((65.0f - sqrtf(4225.0f - 8.0f * (float)t0)) * 0.5f);
    while ((65 * bi - bi * bi) / 2 > t0) bi--;
    while ((65 * (bi + 1) - (bi + 1) * (bi + 1)) / 2 <= t0) bi++;
    const int bj = bi + (t0 - (65 * bi - bi * bi) / 2);
    const int m0 = bi * 128, n0 = bj * 128;
    const bool diag = (bi == bj);

    extern __shared__ char smem[];
    const uint32_t sb = smem_u32(smem);
    const int tid = (int)threadIdx.x;
    const int wid = tid >> 5, lane = tid & 31;
    const int grp = lane >> 2, tig = lane & 3;
    const int mOff = (wid >> 1) * 32;    // warp tile: 32 x 64
    const int nOff = (wid & 1) * 64;
    const int lrow = lane & 15;
    const int lcol = (lane >> 4) & 1;

    if (tid < 128) {
        *(float*)(smem + SM_SQI + tid * 4) = g_sq[m0 + tid];
        *(int*)(smem + SM_LABI + tid * 4) = lab[m0 + tid];
        *(int*)(smem + SM_RNKI + tid * 4) = g_rank[m0 + tid];
    } else {
        int q = tid - 128;
        *(float*)(smem + SM_SQJ + q * 4) = g_sq[n0 + q];
        *(int*)(smem + SM_LABJ + q * 4) = lab[n0 + q];
        *(int*)(smem + SM_RNKJ + q * 4) = g_rank[n0 + q];
    }

    uint32_t acc[2][8][2];   // f16x2 accumulators
    #pragma unroll
    for (int mt = 0; mt < 2; mt++)
        #pragma unroll
        for (int nt = 0; nt < 8; nt++) { acc[mt][nt][0] = 0u; acc[mt][nt][1] = 0u; }

    // 4-stage pipeline, 16 K-chunks of 32, one sync per chunk
    load_chunk(sb + SM_BUF + 0 * STAGE_BYTES, m0, n0, 0, tid);
    load_chunk(sb + SM_BUF + 1 * STAGE_BYTES, m0, n0, 32, tid);
    load_chunk(sb + SM_BUF + 2 * STAGE_BYTES, m0, n0, 64, tid);
    #pragma unroll 1
    for (int c = 0; c < 16; c++) {
        if (c <= 13)      CP_WAIT(2);
        else if (c == 14) CP_WAIT(1);
        else              CP_WAIT(0);
        __syncthreads();   // chunk c visible; also proves MMAs(c-1) complete
        if (c + 3 < 16)    // load into buffer (c+3)%4 == (c-1)%4 — safe after sync
            load_chunk(sb + SM_BUF + ((c + 3) & 3) * STAGE_BYTES, m0, n0, (c + 3) * 32, tid);
        uint32_t Abase = sb + SM_BUF + (c & 3) * STAGE_BYTES;
        uint32_t Bbase = Abase + TILEB;
        #pragma unroll
        for (int ks = 0; ks < 2; ks++) {          // two k16 steps per 32-chunk
            uint32_t a[2][4];
            #pragma unroll
            for (int mt = 0; mt < 2; mt++)
                LDSM_X4(a[mt], Abase + (uint32_t)((mOff + mt * 16 + lrow) * ROWB + ks * 32 + lcol * 16));
            uint32_t b[4][4];
            #pragma unroll
            for (int p = 0; p < 4; p++)
                LDSM_X4(b[p], Bbase + (uint32_t)((nOff + p * 16 + lrow) * ROWB + ks * 32 + lcol * 16));
            #pragma unroll
            for (int p = 0; p < 4; p++) {
                mma_f16acc(acc[0][2 * p],     a[0], b[p][0], b[p][2]);
                mma_f16acc(acc[0][2 * p + 1], a[0], b[p][1], b[p][3]);
                mma_f16acc(acc[1][2 * p],     a[1], b[p][0], b[p][2]);
                mma_f16acc(acc[1][2 * p + 1], a[1], b[p][1], b[p][3]);
            }
        }
    }
    __syncthreads();   // all MMAs done before sd overwrites stage buffers

    // ---------------- epilogue: d -> sd (smem), then row/col scans ----------
    float (*sd)[129] = (float (*)[129])(smem + SM_BUF);
    const float* s_sqi = (const float*)(smem + SM_SQI);
    const float* s_sqj = (const float*)(smem + SM_SQJ);
    const int* s_labi = (const int*)(smem + SM_LABI);
    const int* s_labj = (const int*)(smem + SM_LABJ);
    const int* s_rnki = (const int*)(smem + SM_RNKI);
    const int* s_rnkj = (const int*)(smem + SM_RNKJ);

    #pragma unroll
    for (int mt = 0; mt < 2; mt++) {
        int r0 = mOff + mt * 16 + grp;
        float sq0 = s_sqi[r0], sq1 = s_sqi[r0 + 8];
        #pragma unroll
        for (int nt = 0; nt < 8; nt++) {
            int c0 = nOff + nt * 8 + tig * 2;
            float sqa = s_sqj[c0], sqb = s_sqj[c0 + 1];
            float2 p0 = __half22float2(*reinterpret_cast<__half2*>(&acc[mt][nt][0]));
            float2 p1 = __half22float2(*reinterpret_cast<__half2*>(&acc[mt][nt][1]));
            sd[r0][c0]         = sqrtf(fmaxf(sq0 + sqa - 2.f * p0.x, 0.f) + 1e-12f);
            sd[r0][c0 + 1]     = sqrtf(fmaxf(sq0 + sqb - 2.f * p0.y, 0.f) + 1e-12f);
            sd[r0 + 8][c0]     = sqrtf(fmaxf(sq1 + sqa - 2.f * p1.x, 0.f) + 1e-12f);
            sd[r0 + 8][c0 + 1] = sqrtf(fmaxf(sq1 + sqb - 2.f * p1.y, 0.f) + 1e-12f);
        }
    }
    __syncthreads();

    // row scan: i = m0 + r over tile columns j = n0 + jj
    if (tid < 128) {
        int r = tid, i = m0 + r, li = s_labi[r];
        float rmax = 0.f, nmin = 3.4028235e38f;
        #pragma unroll 4
        for (int jj = 0; jj < 128; jj++) {
            float v = sd[r][jj];
            rmax = fmaxf(rmax, v);
            if (li != s_labj[jj]) {
                nmin = fminf(nmin, v);
            } else {
                g_cd[(size_t)i * CCAP + s_rnkj[jj]] = v;   // deterministic slot
            }
        }
        atomicMax((int*)&g_rowmax[i], __float_as_int(rmax));
        atomicMin((int*)&g_negmin[i], __float_as_int(nmin));
    } else if (!diag) {   // col scan: i = n0 + q over tile rows j = m0 + r
        int q = tid - 128, i = n0 + q, lj = s_labj[q];
        float cmax = 0.f, cnmin = 3.4028235e38f;
        #pragma unroll 4
        for (int r = 0; r < 128; r++) {
            float v = sd[r][q];
            cmax = fmaxf(cmax, v);
            if (s_labi[r] != lj) {
                cnmin = fminf(cnmin, v);
            } else {
                g_cd[(size_t)i * CCAP + s_rnki[r]] = v;
            }
        }
        atomicMax((int*)&g_rowmax[i], __float_as_int(cmax));
        atomicMin((int*)&g_negmin[i], __float_as_int(cnmin));
    }
}

// ---------------------------------------------------------------------------
// Kernel C: block per class. Member list + rowmax staged in smem; contiguous cd.
//   row value = posmax[i] + relu(0.5 - min(negmin[i], corr[i]))
//   corr[i] = min(1e-6 + rowmax[i], min_{s != rank(i)} (cd[i][s] + rm[s]))
//   Last finished block reduces the 64 class partials (fixed order) -> out.
// ---------------------------------------------------------------------------
__global__ void hneg_kernel(const int* __restrict__ lab, float* __restrict__ out) {
    __shared__ int s_mem[CCAP];
    __shared__ float s_rm[CCAP];
    __shared__ float s_wacc[8];
    __shared__ int s_last;
    const int c = blockIdx.x;
    const int tid = (int)threadIdx.x;
    const int warp = tid >> 5, lane = tid & 31;
    const int cnt = g_ccnt[c];

    for (int s = tid; s < cnt; s += 256) {
        int j = g_clist[c * CCAP + s];
        s_mem[s] = j;
        s_rm[s] = g_rowmax[j];
    }
    if (tid < 8) s_wacc[tid] = 0.f;
    __syncthreads();

    // each warp processes rows r = warp, warp+8, ... in order (deterministic)
    float wacc = 0.f;
    for (int r = warp; r < cnt; r += 8) {
        int i = s_mem[r];
        const float* cd = g_cd + (size_t)i * CCAP;
        float pos = 0.f, corr = 3.4028235e38f;
        for (int s = lane; s < cnt; s += 32) {
            if (s != r) {                 // s == r  <=>  j == i
                float d = cd[s];
                pos = fmaxf(pos, d);
                corr = fminf(corr, d + s_rm[s]);
            }
        }
        #pragma unroll
        for (int o = 16; o > 0; o >>= 1) {
            pos = fmaxf(pos, __shfl_xor_sync(0xffffffffu, pos, o));
            corr = fminf(corr, __shfl_xor_sync(0xffffffffu, corr, o));
        }
        if (lane == 0) {
            corr = fminf(corr, 1e-6f + s_rm[r]);   // j == i self term
            float hn = fminf(g_negmin[i], corr);
            wacc += pos + fmaxf(0.5f - hn, 0.f);
        }
    }
    if (lane == 0) s_wacc[warp] = wacc;
    __syncthreads();
    if (tid == 0) {
        float s = 0.f;
        #pragma unroll
        for (int w = 0; w < 8; w++) s += s_wacc[w];   // fixed order
        g_part[c] = s;
        __threadfence();
        s_last = (atomicAdd(&g_done, 1) == 63);
    }
    __syncthreads();
    if (s_last && tid == 0) {
        float t = 0.f;
        #pragma unroll
        for (int q = 0; q < 64; q++) t += g_part[q];  // fixed order: deterministic
        out[0] = t / (float)NROW;
    }
}

// ---------------------------------------------------------------------------
extern "C" void kernel_launch(void* const* d_in, const int* in_sizes, int n_in,
                              void* d_out, int out_size) {
    const float* X = (const float*)d_in[0];
    const int* lab = (const int*)d_in[1];
    float* out = (float*)d_out;

    cudaFuncSetAttribute(dist_kernel, cudaFuncAttributeMaxDynamicSharedMemorySize, SMEM_TOTAL);

    prep_kernel<<<NROW / 2 + 64, 256>>>(X, lab);
    dist_kernel<<<528, 256, SMEM_TOTAL>>>(lab);
    hneg_kernel<<<64, 256>>>(lab, out);
}

// round 15
// speedup vs baseline: 1.2101x; 1.2101x over previous
#include <cuda_runtime.h>
#include <cuda_fp16.h>
#include <cstdint>

#define NROW 4096
#define DDIM 512
#define CCAP 128   // max members per class (mean 64, sd ~8)

// -------------------------- device scratch (no allocs) ----------------------
__device__ float g_sq[NROW];
__device__ float g_rowmax[NROW];   // max_distance per row (atomicMax, reset each call)
__device__ float g_negmin[NROW];   // min dist over diff-label j (atomicMin)
__device__ float g_part[256];      // per-block partial sums of (posmax + pen)
__device__ int   g_clist[64 * CCAP];  // per-class member lists (ordered)
__device__ int   g_ccnt[64];
__device__ int   g_rank[NROW];        // rank of row within its class list
__device__ int   g_done;              // completion counter for fused final reduce
__device__ float g_cd[(size_t)NROW * CCAP];  // compact same-class distances (2 MB)
__device__ __half g_h[(size_t)NROW * DDIM];  // fp16 features

// -------------------------- PTX helpers -------------------------------------
__device__ __forceinline__ uint32_t smem_u32(const void* p) {
    uint32_t a;
    asm("{ .reg .u64 t; cvta.to.shared.u64 t, %1; cvt.u32.u64 %0, t; }" : "=r"(a) : "l"(p));
    return a;
}

#define CP_ASYNC16(dst, src) \
    asm volatile("cp.async.cg.shared.global [%0], [%1], 16;" :: "r"(dst), "l"(src) : "memory")
#define CP_COMMIT() asm volatile("cp.async.commit_group;" ::: "memory")
#define CP_WAIT(n)  asm volatile("cp.async.wait_group %0;" :: "n"(n) : "memory")

#define LDSM_X4(R, addr) \
    asm volatile("ldmatrix.sync.aligned.m8n8.x4.shared.b16 {%0,%1,%2,%3}, [%4];" \
        : "=r"((R)[0]), "=r"((R)[1]), "=r"((R)[2]), "=r"((R)[3]) : "r"(addr))

// D(16x8,f16) += A(16x16 f16, row) * B(16x8 f16, col: B[n][k]) — fp16 accumulator
__device__ __forceinline__ void mma_f16acc(uint32_t* d, const uint32_t* a, uint32_t b0, uint32_t b1) {
    asm volatile(
        "mma.sync.aligned.m16n8k16.row.col.f16.f16.f16.f16 "
        "{%0,%1}, {%2,%3,%4,%5}, {%6,%7}, {%0,%1};"
        : "+r"(d[0]), "+r"(d[1])
        : "r"(a[0]), "r"(a[1]), "r"(a[2]), "r"(a[3]), "r"(b0), "r"(b1));
}

// -------------------------- dist kernel SMEM layout -------------------------
#define SM_SQI   0
#define SM_SQJ   512
#define SM_LABI  1024
#define SM_LABJ  1536
#define SM_RNKI  2048
#define SM_RNKJ  2560
#define SM_BUF   3072
#define ROWB     80                // bytes per smem tile row (32 halves + 8 pad)
#define TILEB    (128 * ROWB)      // 10240
#define STAGE_BYTES (2 * TILEB)    // 20480  (A tile + B tile)
#define NSTAGE   4
#define SMEM_TOTAL (SM_BUF + NSTAGE * STAGE_BYTES)   // 84992 > 3072 + 66048 (sd reuse)

// ---------------------------------------------------------------------------
// Kernel 0: fp16 convert + squared norms + per-call resets (2 rows/block)
// ---------------------------------------------------------------------------
__global__ void conv_kernel(const float* __restrict__ X) {
    int row = blockIdx.x * 2 + (threadIdx.x >> 7);
    int t = threadIdx.x & 127;     // 0..127, one float4 each
    const float4* xr = reinterpret_cast<const float4*>(X + (size_t)row * DDIM);
    float4 v = xr[t];
    float vv[4] = {v.x, v.y, v.z, v.w};
    float s = 0.f;
    __half h[4];
    #pragma unroll
    for (int k = 0; k < 4; k++) { s += vv[k] * vv[k]; h[k] = __float2half_rn(vv[k]); }
    *reinterpret_cast<uint2*>(g_h + (size_t)row * DDIM + t * 4) = *reinterpret_cast<uint2*>(h);
    #pragma unroll
    for (int q = 16; q > 0; q >>= 1) s += __shfl_xor_sync(0xffffffffu, s, q);
    __shared__ float ws[8];
    if ((threadIdx.x & 31) == 0) ws[threadIdx.x >> 5] = s;
    __syncthreads();
    if (t == 0) {
        int w0 = (threadIdx.x >> 7) * 4;
        g_sq[row] = ws[w0] + ws[w0 + 1] + ws[w0 + 2] + ws[w0 + 3];
        g_rowmax[row] = 0.f;
        g_negmin[row] = 3.4028235e38f;
    }
    if (blockIdx.x == 0 && threadIdx.x == 0) g_done = 0;
}

// ---------------------------------------------------------------------------
// Kernel 0b: two-phase ordered class lists (64 blocks x 256 thr, 8 warp strips)
// ---------------------------------------------------------------------------
__global__ void classlist_kernel(const int* __restrict__ lab) {
    __shared__ int s_wcnt[8];
    const int c = blockIdx.x;
    const int warp = threadIdx.x >> 5, lane = threadIdx.x & 31;
    const int base0 = warp * (NROW / 8);           // 512-row strip per warp

    // phase 1: count matches in strip (16 independent ballot steps)
    int cnt = 0;
    #pragma unroll
    for (int it = 0; it < NROW / 8 / 32; it++) {
        bool m = (lab[base0 + it * 32 + lane] == c);
        cnt += __popc(__ballot_sync(0xffffffffu, m));
    }
    if (lane == 0) s_wcnt[warp] = cnt;
    __syncthreads();

    // exclusive prefix over 8 warp counts (computed redundantly per thread)
    int off = 0, tot = 0;
    #pragma unroll
    for (int w = 0; w < 8; w++) { if (w < warp) off += s_wcnt[w]; tot += s_wcnt[w]; }

    // phase 2: rescan strip, write members + ranks at prefix offsets
    int run = off;
    #pragma unroll
    for (int it = 0; it < NROW / 8 / 32; it++) {
        int idx = base0 + it * 32 + lane;
        bool m = (lab[idx] == c);
        unsigned bal = __ballot_sync(0xffffffffu, m);
        if (m) {
            int pos = run + __popc(bal & ((1u << lane) - 1u));
            if (pos < CCAP) { g_clist[c * CCAP + pos] = idx; g_rank[idx] = pos; }
        }
        run += __popc(bal);
    }
    if (threadIdx.x == 0) g_ccnt[c] = tot < CCAP ? tot : CCAP;
}

// ---------------------------------------------------------------------------
// Kernel 1: fp16 mma.sync (fp16 accum) Gram -> stats + compact same-class dists
//   528 upper-triangle tiles, 16 K-chunks of 32, 4-stage pipeline, 1 sync/chunk
// ---------------------------------------------------------------------------
__device__ __forceinline__ void load_chunk(uint32_t stage_base, int m0, int n0, int k0, int tid) {
    #pragma unroll
    for (int t = 0; t < 2; t++) {        // 0 = A rows (m0), 1 = B rows (n0)
        int r0 = t ? n0 : m0;
        uint32_t dbase = stage_base + t * TILEB;
        #pragma unroll
        for (int q = 0; q < 2; q++) {
            int idx = q * 256 + tid;     // 0..511
            int row = idx >> 2;
            int seg = idx & 3;           // 4 x 16B = 32 halves per row
            const __half* gs = g_h + (size_t)(r0 + row) * DDIM + k0 + seg * 8;
            CP_ASYNC16(dbase + (uint32_t)(row * ROWB + seg * 16), gs);
        }
    }
    CP_COMMIT();
}

__global__ __launch_bounds__(256, 2) void dist_kernel(const int* __restrict__ lab) {
    // decode linear tile index -> (bi, bj) with bi <= bj over 32x32 triangle
    const int t0 = (int)blockIdx.x;
    int bi = (int)((65.0f - sqrtf(4225.0f - 8.0f * (float)t0)) * 0.5f);
    while ((65 * bi - bi * bi) / 2 > t0) bi--;
    while ((65 * (bi + 1) - (bi + 1) * (bi + 1)) / 2 <= t0) bi++;
    const int bj = bi + (t0 - (65 * bi - bi * bi) / 2);
    const int m0 = bi * 128, n0 = bj * 128;
    const bool diag = (bi == bj);

    extern __shared__ char smem[];
    const uint32_t sb = smem_u32(smem);
    const int tid = (int)threadIdx.x;
    const int wid = tid >> 5, lane = tid & 31;
    const int grp = lane >> 2, tig = lane & 3;
    const int mOff = (wid >> 1) * 32;    // warp tile: 32 x 64
    const int nOff = (wid & 1) * 64;
    const int lrow = lane & 15;
    const int lcol = (lane >> 4) & 1;

    if (tid < 128) {
        *(float*)(smem + SM_SQI + tid * 4) = g_sq[m0 + tid];
        *(int*)(smem + SM_LABI + tid * 4) = lab[m0 + tid];
        *(int*)(smem + SM_RNKI + tid * 4) = g_rank[m0 + tid];
    } else {
        int q = tid - 128;
        *(float*)(smem + SM_SQJ + q * 4) = g_sq[n0 + q];
        *(int*)(smem + SM_LABJ + q * 4) = lab[n0 + q];
        *(int*)(smem + SM_RNKJ + q * 4) = g_rank[n0 + q];
    }

    uint32_t acc[2][8][2];   // f16x2 accumulators
    #pragma unroll
    for (int mt = 0; mt < 2; mt++)
        #pragma unroll
        for (int nt = 0; nt < 8; nt++) { acc[mt][nt][0] = 0u; acc[mt][nt][1] = 0u; }

    // 4-stage pipeline, 16 K-chunks of 32, one sync per chunk
    load_chunk(sb + SM_BUF + 0 * STAGE_BYTES, m0, n0, 0, tid);
    load_chunk(sb + SM_BUF + 1 * STAGE_BYTES, m0, n0, 32, tid);
    load_chunk(sb + SM_BUF + 2 * STAGE_BYTES, m0, n0, 64, tid);
    #pragma unroll 1
    for (int c = 0; c < 16; c++) {
        if (c <= 13)      CP_WAIT(2);
        else if (c == 14) CP_WAIT(1);
        else              CP_WAIT(0);
        __syncthreads();   // chunk c visible; also proves MMAs(c-1) complete
        if (c + 3 < 16)    // load into buffer (c+3)%4 == (c-1)%4 — safe after sync
            load_chunk(sb + SM_BUF + ((c + 3) & 3) * STAGE_BYTES, m0, n0, (c + 3) * 32, tid);
        uint32_t Abase = sb + SM_BUF + (c & 3) * STAGE_BYTES;
        uint32_t Bbase = Abase + TILEB;
        #pragma unroll
        for (int ks = 0; ks < 2; ks++) {          // two k16 steps per 32-chunk
            uint32_t a[2][4];
            #pragma unroll
            for (int mt = 0; mt < 2; mt++)
                LDSM_X4(a[mt], Abase + (uint32_t)((mOff + mt * 16 + lrow) * ROWB + ks * 32 + lcol * 16));
            uint32_t b[4][4];
            #pragma unroll
            for (int p = 0; p < 4; p++)
                LDSM_X4(b[p], Bbase + (uint32_t)((nOff + p * 16 + lrow) * ROWB + ks * 32 + lcol * 16));
            #pragma unroll
            for (int p = 0; p < 4; p++) {
                mma_f16acc(acc[0][2 * p],     a[0], b[p][0], b[p][2]);
                mma_f16acc(acc[0][2 * p + 1], a[0], b[p][1], b[p][3]);
                mma_f16acc(acc[1][2 * p],     a[1], b[p][0], b[p][2]);
                mma_f16acc(acc[1][2 * p + 1], a[1], b[p][1], b[p][3]);
            }
        }
    }
    __syncthreads();   // all MMAs done before sd overwrites stage buffers

    // ---------------- epilogue: d -> sd (smem), then row/col scans ----------
    float (*sd)[129] = (float (*)[129])(smem + SM_BUF);
    const float* s_sqi = (const float*)(smem + SM_SQI);
    const float* s_sqj = (const float*)(smem + SM_SQJ);
    const int* s_labi = (const int*)(smem + SM_LABI);
    const int* s_labj = (const int*)(smem + SM_LABJ);
    const int* s_rnki = (const int*)(smem + SM_RNKI);
    const int* s_rnkj = (const int*)(smem + SM_RNKJ);

    #pragma unroll
    for (int mt = 0; mt < 2; mt++) {
        int r0 = mOff + mt * 16 + grp;
        float sq0 = s_sqi[r0], sq1 = s_sqi[r0 + 8];
        #pragma unroll
        for (int nt = 0; nt < 8; nt++) {
            int c0 = nOff + nt * 8 + tig * 2;
            float sqa = s_sqj[c0], sqb = s_sqj[c0 + 1];
            float2 p0 = __half22float2(*reinterpret_cast<__half2*>(&acc[mt][nt][0]));
            float2 p1 = __half22float2(*reinterpret_cast<__half2*>(&acc[mt][nt][1]));
            sd[r0][c0]         = sqrtf(fmaxf(sq0 + sqa - 2.f * p0.x, 0.f) + 1e-12f);
            sd[r0][c0 + 1]     = sqrtf(fmaxf(sq0 + sqb - 2.f * p0.y, 0.f) + 1e-12f);
            sd[r0 + 8][c0]     = sqrtf(fmaxf(sq1 + sqa - 2.f * p1.x, 0.f) + 1e-12f);
            sd[r0 + 8][c0 + 1] = sqrtf(fmaxf(sq1 + sqb - 2.f * p1.y, 0.f) + 1e-12f);
        }
    }
    __syncthreads();

    // row scan: i = m0 + r over tile columns j = n0 + jj
    if (tid < 128) {
        int r = tid, i = m0 + r, li = s_labi[r];
        float rmax = 0.f, nmin = 3.4028235e38f;
        #pragma unroll 4
        for (int jj = 0; jj < 128; jj++) {
            float v = sd[r][jj];
            rmax = fmaxf(rmax, v);
            if (li != s_labj[jj]) {
                nmin = fminf(nmin, v);
            } else {
                g_cd[(size_t)i * CCAP + s_rnkj[jj]] = v;   // deterministic slot
            }
        }
        atomicMax((int*)&g_rowmax[i], __float_as_int(rmax));
        atomicMin((int*)&g_negmin[i], __float_as_int(nmin));
    } else if (!diag) {   // col scan: i = n0 + q over tile rows j = m0 + r
        int q = tid - 128, i = n0 + q, lj = s_labj[q];
        float cmax = 0.f, cnmin = 3.4028235e38f;
        #pragma unroll 4
        for (int r = 0; r < 128; r++) {
            float v = sd[r][q];
            cmax = fmaxf(cmax, v);
            if (s_labi[r] != lj) {
                cnmin = fminf(cnmin, v);
            } else {
                g_cd[(size_t)i * CCAP + s_rnki[r]] = v;
            }
        }
        atomicMax((int*)&g_rowmax[i], __float_as_int(cmax));
        atomicMin((int*)&g_negmin[i], __float_as_int(cnmin));
    }
}

// ---------------------------------------------------------------------------
// Kernel 2: warp per row (16 rows/block, 256 blocks) + fused final reduce.
// ---------------------------------------------------------------------------
__global__ void hneg_kernel(const int* __restrict__ lab, float* __restrict__ out) {
    __shared__ float wsum[16];
    __shared__ int s_last;
    int warp = threadIdx.x >> 5;
    int i = blockIdx.x * 16 + warp;
    int lane = threadIdx.x & 31;
    int c = lab[i];
    int cnt = g_ccnt[c];
    const int* mem = g_clist + c * CCAP;
    const float* cd = g_cd + (size_t)i * CCAP;
    float pos = 0.f, corr = 3.4028235e38f;
    for (int s = lane; s < cnt; s += 32) {
        int j = mem[s];
        if (j != i) {
            float d = cd[s];
            pos = fmaxf(pos, d);
            corr = fminf(corr, d + g_rowmax[j]);
        }
    }
    #pragma unroll
    for (int o = 16; o > 0; o >>= 1) {
        pos = fmaxf(pos, __shfl_xor_sync(0xffffffffu, pos, o));
        corr = fminf(corr, __shfl_xor_sync(0xffffffffu, corr, o));
    }
    if (lane == 0) {
        corr = fminf(corr, 1e-6f + g_rowmax[i]);     // j == i self term
        float hn = fminf(g_negmin[i], corr);
        wsum[warp] = pos + fmaxf(0.5f - hn, 0.f);
    }
    __syncthreads();
    if (threadIdx.x == 0) {
        float s = 0.f;
        #pragma unroll
        for (int w = 0; w < 16; w++) s += wsum[w];   // fixed order: deterministic
        g_part[blockIdx.x] = s;
        __threadfence();
        s_last = (atomicAdd(&g_done, 1) == 255);
    }
    __syncthreads();
    if (s_last && threadIdx.x < 32) {
        float s = 0.f;
        #pragma unroll
        for (int q = 0; q < 8; q++) s += g_part[q * 32 + threadIdx.x];
        #pragma unroll
        for (int o = 16; o > 0; o >>= 1) s += __shfl_xor_sync(0xffffffffu, s, o);
        if (threadIdx.x == 0) out[0] = s / (float)NROW;
    }
}

// ---------------------------------------------------------------------------
extern "C" void kernel_launch(void* const* d_in, const int* in_sizes, int n_in,
                              void* d_out, int out_size) {
    const float* X = (const float*)d_in[0];
    const int* lab = (const int*)d_in[1];
    float* out = (float*)d_out;

    cudaFuncSetAttribute(dist_kernel, cudaFuncAttributeMaxDynamicSharedMemorySize, SMEM_TOTAL);

    conv_kernel<<<NROW / 2, 256>>>(X);
    classlist_kernel<<<64, 256>>>(lab);
    dist_kernel<<<528, 256, SMEM_TOTAL>>>(lab);
    hneg_kernel<<<NROW / 16, 512>>>(lab, out);
}

// round 16
// speedup vs baseline: 1.2476x; 1.0310x over previous
#include <cuda_runtime.h>
#include <cuda_fp16.h>
#include <cstdint>

#define NROW 4096
#define DDIM 512
#define CCAP 128   // max members per class (mean 64, sd ~8)

// -------------------------- device scratch (no allocs) ----------------------
__device__ float g_sq[NROW];
__device__ float g_rowmax[NROW];   // max_distance per row (atomicMax, reset each call)
__device__ float g_negmin[NROW];   // min dist over diff-label j (atomicMin)
__device__ float g_part[512];      // per-block partial sums of (posmax + pen)
__device__ int   g_clist[64 * CCAP];  // per-class member lists (ordered)
__device__ int   g_ccnt[64];
__device__ int   g_rank[NROW];        // rank of row within its class list
__device__ int   g_done;              // completion counter for fused final reduce
__device__ float g_cd[(size_t)NROW * CCAP];  // compact same-class distances (2 MB)
__device__ __half g_h[(size_t)NROW * DDIM];  // fp16 features

// -------------------------- PTX helpers -------------------------------------
__device__ __forceinline__ uint32_t smem_u32(const void* p) {
    uint32_t a;
    asm("{ .reg .u64 t; cvta.to.shared.u64 t, %1; cvt.u32.u64 %0, t; }" : "=r"(a) : "l"(p));
    return a;
}

#define CP_ASYNC16(dst, src) \
    asm volatile("cp.async.cg.shared.global [%0], [%1], 16;" :: "r"(dst), "l"(src) : "memory")
#define CP_COMMIT() asm volatile("cp.async.commit_group;" ::: "memory")
#define CP_WAIT(n)  asm volatile("cp.async.wait_group %0;" :: "n"(n) : "memory")

#define LDSM_X4(R, addr) \
    asm volatile("ldmatrix.sync.aligned.m8n8.x4.shared.b16 {%0,%1,%2,%3}, [%4];" \
        : "=r"((R)[0]), "=r"((R)[1]), "=r"((R)[2]), "=r"((R)[3]) : "r"(addr))

// D(16x8,f16) += A(16x16 f16, row) * B(16x8 f16, col: B[n][k]) — fp16 accumulator
__device__ __forceinline__ void mma_f16acc(uint32_t* d, const uint32_t* a, uint32_t b0, uint32_t b1) {
    asm volatile(
        "mma.sync.aligned.m16n8k16.row.col.f16.f16.f16.f16 "
        "{%0,%1}, {%2,%3,%4,%5}, {%6,%7}, {%0,%1};"
        : "+r"(d[0]), "+r"(d[1])
        : "r"(a[0]), "r"(a[1]), "r"(a[2]), "r"(a[3]), "r"(b0), "r"(b1));
}

// -------------------------- dist kernel SMEM layout -------------------------
#define SM_SQI   0
#define SM_SQJ   512
#define SM_LABI  1024
#define SM_LABJ  1536
#define SM_RNKI  2048
#define SM_RNKJ  2560
#define SM_BUF   3072
#define ROWB     80                // bytes per smem tile row (32 halves + 8 pad)
#define TILEB    (128 * ROWB)      // 10240
#define STAGE_BYTES (2 * TILEB)    // 20480  (A tile + B tile)
#define NSTAGE   4
#define SDW      132               // sd row stride in floats (16B-aligned rows)
#define SMEM_TOTAL (SM_BUF + NSTAGE * STAGE_BYTES)   // 84992 > 3072 + 128*132*4 = 70656

// ---------------------------------------------------------------------------
// Kernel A: fused prep.
//   blocks 0..2047:  fp16 convert + squared norms + stat reset (2 rows/block)
//   blocks 2048..2111: two-phase ordered class list for class (b-2048)
// ---------------------------------------------------------------------------
__global__ void prep_kernel(const float* __restrict__ X, const int* __restrict__ lab) {
    if (blockIdx.x < NROW / 2) {
        int row = blockIdx.x * 2 + (threadIdx.x >> 7);
        int t = threadIdx.x & 127;     // 0..127, one float4 each
        const float4* xr = reinterpret_cast<const float4*>(X + (size_t)row * DDIM);
        float4 v = xr[t];
        float vv[4] = {v.x, v.y, v.z, v.w};
        float s = 0.f;
        __half h[4];
        #pragma unroll
        for (int k = 0; k < 4; k++) { s += vv[k] * vv[k]; h[k] = __float2half_rn(vv[k]); }
        *reinterpret_cast<uint2*>(g_h + (size_t)row * DDIM + t * 4) = *reinterpret_cast<uint2*>(h);
        #pragma unroll
        for (int q = 16; q > 0; q >>= 1) s += __shfl_xor_sync(0xffffffffu, s, q);
        __shared__ float ws[8];
        if ((threadIdx.x & 31) == 0) ws[threadIdx.x >> 5] = s;
        __syncthreads();
        if (t == 0) {
            int w0 = (threadIdx.x >> 7) * 4;
            g_sq[row] = ws[w0] + ws[w0 + 1] + ws[w0 + 2] + ws[w0 + 3];
            g_rowmax[row] = 0.f;
            g_negmin[row] = 3.4028235e38f;
        }
        if (blockIdx.x == 0 && threadIdx.x == 0) g_done = 0;
    } else {
        // two-phase ordered class list (8 warp strips of 512 rows)
        __shared__ int s_wcnt[8];
        const int c = blockIdx.x - NROW / 2;
        const int warp = threadIdx.x >> 5, lane = threadIdx.x & 31;
        const int base0 = warp * (NROW / 8);

        int cnt = 0;
        #pragma unroll
        for (int it = 0; it < NROW / 8 / 32; it++) {
            bool m = (lab[base0 + it * 32 + lane] == c);
            cnt += __popc(__ballot_sync(0xffffffffu, m));
        }
        if (lane == 0) s_wcnt[warp] = cnt;
        __syncthreads();

        int off = 0, tot = 0;
        #pragma unroll
        for (int w = 0; w < 8; w++) { if (w < warp) off += s_wcnt[w]; tot += s_wcnt[w]; }

        int run = off;
        #pragma unroll
        for (int it = 0; it < NROW / 8 / 32; it++) {
            int idx = base0 + it * 32 + lane;
            bool m = (lab[idx] == c);
            unsigned bal = __ballot_sync(0xffffffffu, m);
            if (m) {
                int pos = run + __popc(bal & ((1u << lane) - 1u));
                if (pos < CCAP) { g_clist[c * CCAP + pos] = idx; g_rank[idx] = pos; }
            }
            run += __popc(bal);
        }
        if (threadIdx.x == 0) g_ccnt[c] = tot < CCAP ? tot : CCAP;
    }
}

// ---------------------------------------------------------------------------
// Kernel B: fp16 mma.sync (fp16 accum) Gram -> stats + compact same-class dists
//   528 upper-triangle tiles, 16 K-chunks of 32, 4-stage pipeline, 1 sync/chunk
// ---------------------------------------------------------------------------
__device__ __forceinline__ void load_chunk(uint32_t stage_base, int m0, int n0, int k0, int tid) {
    #pragma unroll
    for (int t = 0; t < 2; t++) {        // 0 = A rows (m0), 1 = B rows (n0)
        int r0 = t ? n0 : m0;
        uint32_t dbase = stage_base + t * TILEB;
        #pragma unroll
        for (int q = 0; q < 2; q++) {
            int idx = q * 256 + tid;     // 0..511
            int row = idx >> 2;
            int seg = idx & 3;           // 4 x 16B = 32 halves per row
            const __half* gs = g_h + (size_t)(r0 + row) * DDIM + k0 + seg * 8;
            CP_ASYNC16(dbase + (uint32_t)(row * ROWB + seg * 16), gs);
        }
    }
    CP_COMMIT();
}

__global__ __launch_bounds__(256, 2) void dist_kernel(const int* __restrict__ lab) {
    // decode linear tile index -> (bi, bj) with bi <= bj over 32x32 triangle
    const int t0 = (int)blockIdx.x;
    int bi = (int)((65.0f - sqrtf(4225.0f - 8.0f * (float)t0)) * 0.5f);
    while ((65 * bi - bi * bi) / 2 > t0) bi--;
    while ((65 * (bi + 1) - (bi + 1) * (bi + 1)) / 2 <= t0) bi++;
    const int bj = bi + (t0 - (65 * bi - bi * bi) / 2);
    const int m0 = bi * 128, n0 = bj * 128;
    const bool diag = (bi == bj);

    extern __shared__ char smem[];
    const uint32_t sb = smem_u32(smem);
    const int tid = (int)threadIdx.x;
    const int wid = tid >> 5, lane = tid & 31;
    const int grp = lane >> 2, tig = lane & 3;
    const int mOff = (wid >> 1) * 32;    // warp tile: 32 x 64
    const int nOff = (wid & 1) * 64;
    const int lrow = lane & 15;
    const int lcol = (lane >> 4) & 1;

    if (tid < 128) {
        *(float*)(smem + SM_SQI + tid * 4) = g_sq[m0 + tid];
        *(int*)(smem + SM_LABI + tid * 4) = lab[m0 + tid];
        *(int*)(smem + SM_RNKI + tid * 4) = g_rank[m0 + tid];
    } else {
        int q = tid - 128;
        *(float*)(smem + SM_SQJ + q * 4) = g_sq[n0 + q];
        *(int*)(smem + SM_LABJ + q * 4) = lab[n0 + q];
        *(int*)(smem + SM_RNKJ + q * 4) = g_rank[n0 + q];
    }

    uint32_t acc[2][8][2];   // f16x2 accumulators
    #pragma unroll
    for (int mt = 0; mt < 2; mt++)
        #pragma unroll
        for (int nt = 0; nt < 8; nt++) { acc[mt][nt][0] = 0u; acc[mt][nt][1] = 0u; }

    // 4-stage pipeline, 16 K-chunks of 32, one sync per chunk
    load_chunk(sb + SM_BUF + 0 * STAGE_BYTES, m0, n0, 0, tid);
    load_chunk(sb + SM_BUF + 1 * STAGE_BYTES, m0, n0, 32, tid);
    load_chunk(sb + SM_BUF + 2 * STAGE_BYTES, m0, n0, 64, tid);
    #pragma unroll 1
    for (int c = 0; c < 16; c++) {
        if (c <= 13)      CP_WAIT(2);
        else if (c == 14) CP_WAIT(1);
        else              CP_WAIT(0);
        __syncthreads();   // chunk c visible; also proves MMAs(c-1) complete
        if (c + 3 < 16)    // load into buffer (c+3)%4 == (c-1)%4 — safe after sync
            load_chunk(sb + SM_BUF + ((c + 3) & 3) * STAGE_BYTES, m0, n0, (c + 3) * 32, tid);
        uint32_t Abase = sb + SM_BUF + (c & 3) * STAGE_BYTES;
        uint32_t Bbase = Abase + TILEB;
        #pragma unroll
        for (int ks = 0; ks < 2; ks++) {          // two k16 steps per 32-chunk
            uint32_t a[2][4];
            #pragma unroll
            for (int mt = 0; mt < 2; mt++)
                LDSM_X4(a[mt], Abase + (uint32_t)((mOff + mt * 16 + lrow) * ROWB + ks * 32 + lcol * 16));
            uint32_t b[4][4];
            #pragma unroll
            for (int p = 0; p < 4; p++)
                LDSM_X4(b[p], Bbase + (uint32_t)((nOff + p * 16 + lrow) * ROWB + ks * 32 + lcol * 16));
            #pragma unroll
            for (int p = 0; p < 4; p++) {
                mma_f16acc(acc[0][2 * p],     a[0], b[p][0], b[p][2]);
                mma_f16acc(acc[0][2 * p + 1], a[0], b[p][1], b[p][3]);
                mma_f16acc(acc[1][2 * p],     a[1], b[p][0], b[p][2]);
                mma_f16acc(acc[1][2 * p + 1], a[1], b[p][1], b[p][3]);
            }
        }
    }
    __syncthreads();   // all MMAs done before sd overwrites stage buffers

    // ---------------- epilogue: d -> sd (smem), then row/col scans ----------
    float (*sd)[SDW] = (float (*)[SDW])(smem + SM_BUF);
    const float* s_sqi = (const float*)(smem + SM_SQI);
    const float* s_sqj = (const float*)(smem + SM_SQJ);
    const int* s_labi = (const int*)(smem + SM_LABI);
    const int* s_labj = (const int*)(smem + SM_LABJ);
    const int* s_rnki = (const int*)(smem + SM_RNKI);
    const int* s_rnkj = (const int*)(smem + SM_RNKJ);

    #pragma unroll
    for (int mt = 0; mt < 2; mt++) {
        int r0 = mOff + mt * 16 + grp;
        float sq0 = s_sqi[r0], sq1 = s_sqi[r0 + 8];
        #pragma unroll
        for (int nt = 0; nt < 8; nt++) {
            int c0 = nOff + nt * 8 + tig * 2;
            float sqa = s_sqj[c0], sqb = s_sqj[c0 + 1];
            float2 p0 = __half22float2(*reinterpret_cast<__half2*>(&acc[mt][nt][0]));
            float2 p1 = __half22float2(*reinterpret_cast<__half2*>(&acc[mt][nt][1]));
            sd[r0][c0]         = sqrtf(fmaxf(sq0 + sqa - 2.f * p0.x, 0.f) + 1e-12f);
            sd[r0][c0 + 1]     = sqrtf(fmaxf(sq0 + sqb - 2.f * p0.y, 0.f) + 1e-12f);
            sd[r0 + 8][c0]     = sqrtf(fmaxf(sq1 + sqa - 2.f * p1.x, 0.f) + 1e-12f);
            sd[r0 + 8][c0 + 1] = sqrtf(fmaxf(sq1 + sqb - 2.f * p1.y, 0.f) + 1e-12f);
        }
    }
    __syncthreads();

    // row scan (vectorized): i = m0 + r over tile columns j = n0 + jj
    if (tid < 128) {
        int r = tid, i = m0 + r, li = s_labi[r];
        float rmax = 0.f, nmin = 3.4028235e38f;
        const float4* row4 = reinterpret_cast<const float4*>(sd[r]);
        const int4* lab4 = reinterpret_cast<const int4*>(s_labj);
        #pragma unroll 4
        for (int q4 = 0; q4 < 32; q4++) {
            float4 v = row4[q4];
            int4 lj = lab4[q4];
            rmax = fmaxf(rmax, fmaxf(fmaxf(v.x, v.y), fmaxf(v.z, v.w)));
            if (li != lj.x) nmin = fminf(nmin, v.x);
            else g_cd[(size_t)i * CCAP + s_rnkj[q4 * 4 + 0]] = v.x;
            if (li != lj.y) nmin = fminf(nmin, v.y);
            else g_cd[(size_t)i * CCAP + s_rnkj[q4 * 4 + 1]] = v.y;
            if (li != lj.z) nmin = fminf(nmin, v.z);
            else g_cd[(size_t)i * CCAP + s_rnkj[q4 * 4 + 2]] = v.z;
            if (li != lj.w) nmin = fminf(nmin, v.w);
            else g_cd[(size_t)i * CCAP + s_rnkj[q4 * 4 + 3]] = v.w;
        }
        // diagonal element was stored into cd on diag tiles via label match (i==j):
        // fix: for diag tiles, the i==j element has li == lj; it was written to
        // cd slot rank(i) — that slot is the self slot, skipped by consumers (s != rank(i)).
        // nmin unaffected (li == lj skips it). rmax includes d(i,i)=1e-6, harmless.
        atomicMax((int*)&g_rowmax[i], __float_as_int(rmax));
        atomicMin((int*)&g_negmin[i], __float_as_int(nmin));
    } else if (!diag) {   // col scan: i = n0 + q over tile rows j = m0 + r
        int q = tid - 128, i = n0 + q, lj = s_labj[q];
        float cmax = 0.f, cnmin = 3.4028235e38f;
        #pragma unroll 4
        for (int r = 0; r < 128; r++) {
            float v = sd[r][q];
            cmax = fmaxf(cmax, v);
            if (s_labi[r] != lj) {
                cnmin = fminf(cnmin, v);
            } else {
                g_cd[(size_t)i * CCAP + s_rnki[r]] = v;
            }
        }
        atomicMax((int*)&g_rowmax[i], __float_as_int(cmax));
        atomicMin((int*)&g_negmin[i], __float_as_int(cnmin));
    }
}

// ---------------------------------------------------------------------------
// Kernel C: warp per row (8 rows/block, 512 blocks) + fused final reduce.
//   posmax[i] = max_{s != rank(i)} cd[i][s]
//   corr[i]   = min(1e-6 + rowmax[i], min_{s != rank(i)} (cd[i][s] + rowmax[mem[s]]))
//   pen[i]    = relu(0.5 - min(negmin[i], corr[i]))
// ---------------------------------------------------------------------------
__global__ void hneg_kernel(const int* __restrict__ lab, float* __restrict__ out) {
    __shared__ float wsum[8];
    __shared__ int s_last;
    int warp = threadIdx.x >> 5;
    int i = blockIdx.x * 8 + warp;
    int lane = threadIdx.x & 31;
    int c = lab[i];
    int cnt = g_ccnt[c];
    int ri = g_rank[i];
    const int* mem = g_clist + c * CCAP;
    const float* cd = g_cd + (size_t)i * CCAP;
    float pos = 0.f, corr = 3.4028235e38f;
    for (int s = lane; s < cnt; s += 32) {
        if (s != ri) {
            float d = cd[s];
            pos = fmaxf(pos, d);
            corr = fminf(corr, d + g_rowmax[mem[s]]);
        }
    }
    #pragma unroll
    for (int o = 16; o > 0; o >>= 1) {
        pos = fmaxf(pos, __shfl_xor_sync(0xffffffffu, pos, o));
        corr = fminf(corr, __shfl_xor_sync(0xffffffffu, corr, o));
    }
    if (lane == 0) {
        corr = fminf(corr, 1e-6f + g_rowmax[i]);     // j == i self term
        float hn = fminf(g_negmin[i], corr);
        wsum[warp] = pos + fmaxf(0.5f - hn, 0.f);
    }
    __syncthreads();
    if (threadIdx.x == 0) {
        float s = 0.f;
        #pragma unroll
        for (int w = 0; w < 8; w++) s += wsum[w];    // fixed order: deterministic
        g_part[blockIdx.x] = s;
        __threadfence();
        s_last = (atomicAdd(&g_done, 1) == 511);
    }
    __syncthreads();
    if (s_last && threadIdx.x < 32) {
        float s = 0.f;
        #pragma unroll
        for (int q = 0; q < 16; q++) s += g_part[q * 32 + threadIdx.x];
        #pragma unroll
        for (int o = 16; o > 0; o >>= 1) s += __shfl_xor_sync(0xffffffffu, s, o);
        if (threadIdx.x == 0) out[0] = s / (float)NROW;
    }
}

// ---------------------------------------------------------------------------
extern "C" void kernel_launch(void* const* d_in, const int* in_sizes, int n_in,
                              void* d_out, int out_size) {
    const float* X = (const float*)d_in[0];
    const int* lab = (const int*)d_in[1];
    float* out = (float*)d_out;

    cudaFuncSetAttribute(dist_kernel, cudaFuncAttributeMaxDynamicSharedMemorySize, SMEM_TOTAL);

    prep_kernel<<<NROW / 2 + 64, 256>>>(X, lab);
    dist_kernel<<<528, 256, SMEM_TOTAL>>>(lab);
    hneg_kernel<<<NROW / 8, 256>>>(lab, out);
}

// round 17
// speedup vs baseline: 1.2555x; 1.0063x over previous
#include <cuda_runtime.h>
#include <cuda_fp16.h>
#include <cstdint>

#define NROW 4096
#define DDIM 512
#define CCAP 128   // max members per class (mean 64, sd ~8)

// -------------------------- device scratch (no allocs) ----------------------
__device__ float g_sq[NROW];
__device__ float g_rowmax[NROW];   // max_distance per row (atomicMax, reset each call)
__device__ float g_negmin[NROW];   // min dist over diff-label j (atomicMin)
__device__ float g_part[512];      // per-block partial sums of (posmax + pen)
__device__ int   g_clist[64 * CCAP];  // per-class member lists (ordered)
__device__ int   g_ccnt[64];
__device__ int   g_rank[NROW];        // rank of row within its class list
__device__ int   g_done;              // completion counter for fused final reduce
__device__ float g_cd[(size_t)NROW * CCAP];  // compact same-class distances (2 MB)
__device__ __half g_h[(size_t)NROW * DDIM];  // fp16 features

// -------------------------- PTX helpers -------------------------------------
__device__ __forceinline__ uint32_t smem_u32(const void* p) {
    uint32_t a;
    asm("{ .reg .u64 t; cvta.to.shared.u64 t, %1; cvt.u32.u64 %0, t; }" : "=r"(a) : "l"(p));
    return a;
}

#define CP_ASYNC16(dst, src) \
    asm volatile("cp.async.cg.shared.global [%0], [%1], 16;" :: "r"(dst), "l"(src) : "memory")
#define CP_COMMIT() asm volatile("cp.async.commit_group;" ::: "memory")
#define CP_WAIT(n)  asm volatile("cp.async.wait_group %0;" :: "n"(n) : "memory")

#define LDSM_X4(R, addr) \
    asm volatile("ldmatrix.sync.aligned.m8n8.x4.shared.b16 {%0,%1,%2,%3}, [%4];" \
        : "=r"((R)[0]), "=r"((R)[1]), "=r"((R)[2]), "=r"((R)[3]) : "r"(addr))

// D(16x8,f16) += A(16x16 f16, row) * B(16x8 f16, col: B[n][k]) — fp16 accumulator
__device__ __forceinline__ void mma_f16acc(uint32_t* d, const uint32_t* a, uint32_t b0, uint32_t b1) {
    asm volatile(
        "mma.sync.aligned.m16n8k16.row.col.f16.f16.f16.f16 "
        "{%0,%1}, {%2,%3,%4,%5}, {%6,%7}, {%0,%1};"
        : "+r"(d[0]), "+r"(d[1])
        : "r"(a[0]), "r"(a[1]), "r"(a[2]), "r"(a[3]), "r"(b0), "r"(b1));
}

// -------------------------- dist kernel SMEM layout -------------------------
#define SM_SQI   0
#define SM_SQJ   512
#define SM_LABI  1024
#define SM_LABJ  1536
#define SM_RNKI  2048
#define SM_RNKJ  2560
#define SM_BUF   3072
#define ROWB     80                // bytes per smem tile row (32 halves + 8 pad)
#define TILEB    (128 * ROWB)      // 10240
#define STAGE_BYTES (2 * TILEB)    // 20480  (A tile + B tile)
#define NSTAGE   4
#define SDW      132               // sd row stride in floats (16B-aligned rows)
#define SMEM_TOTAL (SM_BUF + NSTAGE * STAGE_BYTES)   // 84992 > 3072 + 128*132*4 = 70656

// ---------------------------------------------------------------------------
// Kernel A: fused prep.
//   blocks 0..511:   fp16 convert + squared norms + stat reset (8 rows/block,
//                    warp-per-row, 4 independent float4 loads per lane: MLP=4)
//   blocks 512..575: two-phase ordered class list for class (b-512)
// ---------------------------------------------------------------------------
__global__ void prep_kernel(const float* __restrict__ X, const int* __restrict__ lab) {
    if (blockIdx.x < NROW / 8) {
        int warp = threadIdx.x >> 5, lane = threadIdx.x & 31;
        int row = blockIdx.x * 8 + warp;
        const float4* xr = reinterpret_cast<const float4*>(X + (size_t)row * DDIM);
        uint2* hw = reinterpret_cast<uint2*>(g_h + (size_t)row * DDIM);
        float4 v[4];
        #pragma unroll
        for (int k = 0; k < 4; k++) v[k] = xr[lane + k * 32];   // 4 in-flight loads
        float s = 0.f;
        #pragma unroll
        for (int k = 0; k < 4; k++) {
            float vv[4] = {v[k].x, v[k].y, v[k].z, v[k].w};
            __half h[4];
            #pragma unroll
            for (int e = 0; e < 4; e++) { s += vv[e] * vv[e]; h[e] = __float2half_rn(vv[e]); }
            hw[lane + k * 32] = *reinterpret_cast<uint2*>(h);
        }
        #pragma unroll
        for (int q = 16; q > 0; q >>= 1) s += __shfl_xor_sync(0xffffffffu, s, q);
        if (lane == 0) {
            g_sq[row] = s;
            g_rowmax[row] = 0.f;
            g_negmin[row] = 3.4028235e38f;
        }
        if (blockIdx.x == 0 && threadIdx.x == 0) g_done = 0;
    } else {
        // two-phase ordered class list (8 warp strips of 512 rows)
        __shared__ int s_wcnt[8];
        const int c = blockIdx.x - NROW / 8;
        const int warp = threadIdx.x >> 5, lane = threadIdx.x & 31;
        const int base0 = warp * (NROW / 8);

        int cnt = 0;
        #pragma unroll
        for (int it = 0; it < NROW / 8 / 32; it++) {
            bool m = (lab[base0 + it * 32 + lane] == c);
            cnt += __popc(__ballot_sync(0xffffffffu, m));
        }
        if (lane == 0) s_wcnt[warp] = cnt;
        __syncthreads();

        int off = 0, tot = 0;
        #pragma unroll
        for (int w = 0; w < 8; w++) { if (w < warp) off += s_wcnt[w]; tot += s_wcnt[w]; }

        int run = off;
        #pragma unroll
        for (int it = 0; it < NROW / 8 / 32; it++) {
            int idx = base0 + it * 32 + lane;
            bool m = (lab[idx] == c);
            unsigned bal = __ballot_sync(0xffffffffu, m);
            if (m) {
                int pos = run + __popc(bal & ((1u << lane) - 1u));
                if (pos < CCAP) { g_clist[c * CCAP + pos] = idx; g_rank[idx] = pos; }
            }
            run += __popc(bal);
        }
        if (threadIdx.x == 0) g_ccnt[c] = tot < CCAP ? tot : CCAP;
    }
}

// ---------------------------------------------------------------------------
// Kernel B: fp16 mma.sync (fp16 accum) Gram -> stats + compact same-class dists
//   528 upper-triangle tiles, 16 K-chunks of 32, 4-stage pipeline, 1 sync/chunk
// ---------------------------------------------------------------------------
__device__ __forceinline__ void load_chunk(uint32_t stage_base, int m0, int n0, int k0, int tid) {
    #pragma unroll
    for (int t = 0; t < 2; t++) {        // 0 = A rows (m0), 1 = B rows (n0)
        int r0 = t ? n0 : m0;
        uint32_t dbase = stage_base + t * TILEB;
        #pragma unroll
        for (int q = 0; q < 2; q++) {
            int idx = q * 256 + tid;     // 0..511
            int row = idx >> 2;
            int seg = idx & 3;           // 4 x 16B = 32 halves per row
            const __half* gs = g_h + (size_t)(r0 + row) * DDIM + k0 + seg * 8;
            CP_ASYNC16(dbase + (uint32_t)(row * ROWB + seg * 16), gs);
        }
    }
    CP_COMMIT();
}

__global__ __launch_bounds__(256, 2) void dist_kernel(const int* __restrict__ lab) {
    // decode linear tile index -> (bi, bj) with bi <= bj over 32x32 triangle
    const int t0 = (int)blockIdx.x;
    int bi = (int)((65.0f - sqrtf(4225.0f - 8.0f * (float)t0)) * 0.5f);
    while ((65 * bi - bi * bi) / 2 > t0) bi--;
    while ((65 * (bi + 1) - (bi + 1) * (bi + 1)) / 2 <= t0) bi++;
    const int bj = bi + (t0 - (65 * bi - bi * bi) / 2);
    const int m0 = bi * 128, n0 = bj * 128;
    const bool diag = (bi == bj);

    extern __shared__ char smem[];
    const uint32_t sb = smem_u32(smem);
    const int tid = (int)threadIdx.x;
    const int wid = tid >> 5, lane = tid & 31;
    const int grp = lane >> 2, tig = lane & 3;
    const int mOff = (wid >> 1) * 32;    // warp tile: 32 x 64
    const int nOff = (wid & 1) * 64;
    const int lrow = lane & 15;
    const int lcol = (lane >> 4) & 1;

    if (tid < 128) {
        *(float*)(smem + SM_SQI + tid * 4) = g_sq[m0 + tid];
        *(int*)(smem + SM_LABI + tid * 4) = lab[m0 + tid];
        *(int*)(smem + SM_RNKI + tid * 4) = g_rank[m0 + tid];
    } else {
        int q = tid - 128;
        *(float*)(smem + SM_SQJ + q * 4) = g_sq[n0 + q];
        *(int*)(smem + SM_LABJ + q * 4) = lab[n0 + q];
        *(int*)(smem + SM_RNKJ + q * 4) = g_rank[n0 + q];
    }

    uint32_t acc[2][8][2];   // f16x2 accumulators
    #pragma unroll
    for (int mt = 0; mt < 2; mt++)
        #pragma unroll
        for (int nt = 0; nt < 8; nt++) { acc[mt][nt][0] = 0u; acc[mt][nt][1] = 0u; }

    // 4-stage pipeline, 16 K-chunks of 32, one sync per chunk
    load_chunk(sb + SM_BUF + 0 * STAGE_BYTES, m0, n0, 0, tid);
    load_chunk(sb + SM_BUF + 1 * STAGE_BYTES, m0, n0, 32, tid);
    load_chunk(sb + SM_BUF + 2 * STAGE_BYTES, m0, n0, 64, tid);
    #pragma unroll 1
    for (int c = 0; c < 16; c++) {
        if (c <= 13)      CP_WAIT(2);
        else if (c == 14) CP_WAIT(1);
        else              CP_WAIT(0);
        __syncthreads();   // chunk c visible; also proves MMAs(c-1) complete
        if (c + 3 < 16)    // load into buffer (c+3)%4 == (c-1)%4 — safe after sync
            load_chunk(sb + SM_BUF + ((c + 3) & 3) * STAGE_BYTES, m0, n0, (c + 3) * 32, tid);
        uint32_t Abase = sb + SM_BUF + (c & 3) * STAGE_BYTES;
        uint32_t Bbase = Abase + TILEB;
        #pragma unroll
        for (int ks = 0; ks < 2; ks++) {          // two k16 steps per 32-chunk
            uint32_t a[2][4];
            #pragma unroll
            for (int mt = 0; mt < 2; mt++)
                LDSM_X4(a[mt], Abase + (uint32_t)((mOff + mt * 16 + lrow) * ROWB + ks * 32 + lcol * 16));
            uint32_t b[4][4];
            #pragma unroll
            for (int p = 0; p < 4; p++)
                LDSM_X4(b[p], Bbase + (uint32_t)((nOff + p * 16 + lrow) * ROWB + ks * 32 + lcol * 16));
            #pragma unroll
            for (int p = 0; p < 4; p++) {
                mma_f16acc(acc[0][2 * p],     a[0], b[p][0], b[p][2]);
                mma_f16acc(acc[0][2 * p + 1], a[0], b[p][1], b[p][3]);
                mma_f16acc(acc[1][2 * p],     a[1], b[p][0], b[p][2]);
                mma_f16acc(acc[1][2 * p + 1], a[1], b[p][1], b[p][3]);
            }
        }
    }
    __syncthreads();   // all MMAs done before sd overwrites stage buffers

    // ---------------- epilogue: d -> sd (smem), then row/col scans ----------
    float (*sd)[SDW] = (float (*)[SDW])(smem + SM_BUF);
    const float* s_sqi = (const float*)(smem + SM_SQI);
    const float* s_sqj = (const float*)(smem + SM_SQJ);
    const int* s_labi = (const int*)(smem + SM_LABI);
    const int* s_labj = (const int*)(smem + SM_LABJ);
    const int* s_rnki = (const int*)(smem + SM_RNKI);
    const int* s_rnkj = (const int*)(smem + SM_RNKJ);

    #pragma unroll
    for (int mt = 0; mt < 2; mt++) {
        int r0 = mOff + mt * 16 + grp;
        float sq0 = s_sqi[r0], sq1 = s_sqi[r0 + 8];
        #pragma unroll
        for (int nt = 0; nt < 8; nt++) {
            int c0 = nOff + nt * 8 + tig * 2;
            float sqa = s_sqj[c0], sqb = s_sqj[c0 + 1];
            float2 p0 = __half22float2(*reinterpret_cast<__half2*>(&acc[mt][nt][0]));
            float2 p1 = __half22float2(*reinterpret_cast<__half2*>(&acc[mt][nt][1]));
            sd[r0][c0]         = sqrtf(fmaxf(sq0 + sqa - 2.f * p0.x, 0.f) + 1e-12f);
            sd[r0][c0 + 1]     = sqrtf(fmaxf(sq0 + sqb - 2.f * p0.y, 0.f) + 1e-12f);
            sd[r0 + 8][c0]     = sqrtf(fmaxf(sq1 + sqa - 2.f * p1.x, 0.f) + 1e-12f);
            sd[r0 + 8][c0 + 1] = sqrtf(fmaxf(sq1 + sqb - 2.f * p1.y, 0.f) + 1e-12f);
        }
    }
    __syncthreads();

    // row scan (vectorized): i = m0 + r over tile columns j = n0 + jj
    if (tid < 128) {
        int r = tid, i = m0 + r, li = s_labi[r];
        float rmax = 0.f, nmin = 3.4028235e38f;
        const float4* row4 = reinterpret_cast<const float4*>(sd[r]);
        const int4* lab4 = reinterpret_cast<const int4*>(s_labj);
        #pragma unroll 4
        for (int q4 = 0; q4 < 32; q4++) {
            float4 v = row4[q4];
            int4 lj = lab4[q4];
            rmax = fmaxf(rmax, fmaxf(fmaxf(v.x, v.y), fmaxf(v.z, v.w)));
            if (li != lj.x) nmin = fminf(nmin, v.x);
            else g_cd[(size_t)i * CCAP + s_rnkj[q4 * 4 + 0]] = v.x;
            if (li != lj.y) nmin = fminf(nmin, v.y);
            else g_cd[(size_t)i * CCAP + s_rnkj[q4 * 4 + 1]] = v.y;
            if (li != lj.z) nmin = fminf(nmin, v.z);
            else g_cd[(size_t)i * CCAP + s_rnkj[q4 * 4 + 2]] = v.z;
            if (li != lj.w) nmin = fminf(nmin, v.w);
            else g_cd[(size_t)i * CCAP + s_rnkj[q4 * 4 + 3]] = v.w;
        }
        // diag tile self element (i==j) goes to cd slot rank(i) — the self slot,
        // skipped by consumers (s != rank(i)). nmin unaffected; rmax includes 1e-6.
        atomicMax((int*)&g_rowmax[i], __float_as_int(rmax));
        atomicMin((int*)&g_negmin[i], __float_as_int(nmin));
    } else if (!diag) {   // col scan: i = n0 + q over tile rows j = m0 + r
        int q = tid - 128, i = n0 + q, lj = s_labj[q];
        float cmax = 0.f, cnmin = 3.4028235e38f;
        #pragma unroll 4
        for (int r = 0; r < 128; r++) {
            float v = sd[r][q];
            cmax = fmaxf(cmax, v);
            if (s_labi[r] != lj) {
                cnmin = fminf(cnmin, v);
            } else {
                g_cd[(size_t)i * CCAP + s_rnki[r]] = v;
            }
        }
        atomicMax((int*)&g_rowmax[i], __float_as_int(cmax));
        atomicMin((int*)&g_negmin[i], __float_as_int(cnmin));
    }
}

// ---------------------------------------------------------------------------
// Kernel C: warp per row (8 rows/block, 512 blocks) + fused final reduce.
// ---------------------------------------------------------------------------
__global__ void hneg_kernel(const int* __restrict__ lab, float* __restrict__ out) {
    __shared__ float wsum[8];
    __shared__ int s_last;
    int warp = threadIdx.x >> 5;
    int i = blockIdx.x * 8 + warp;
    int lane = threadIdx.x & 31;
    int c = lab[i];
    int cnt = g_ccnt[c];
    int ri = g_rank[i];
    const int* mem = g_clist + c * CCAP;
    const float* cd = g_cd + (size_t)i * CCAP;
    float pos = 0.f, corr = 3.4028235e38f;
    for (int s = lane; s < cnt; s += 32) {
        if (s != ri) {
            float d = cd[s];
            pos = fmaxf(pos, d);
            corr = fminf(corr, d + g_rowmax[mem[s]]);
        }
    }
    #pragma unroll
    for (int o = 16; o > 0; o >>= 1) {
        pos = fmaxf(pos, __shfl_xor_sync(0xffffffffu, pos, o));
        corr = fminf(corr, __shfl_xor_sync(0xffffffffu, corr, o));
    }
    if (lane == 0) {
        corr = fminf(corr, 1e-6f + g_rowmax[i]);     // j == i self term
        float hn = fminf(g_negmin[i], corr);
        wsum[warp] = pos + fmaxf(0.5f - hn, 0.f);
    }
    __syncthreads();
    if (threadIdx.x == 0) {
        float s = 0.f;
        #pragma unroll
        for (int w = 0; w < 8; w++) s += wsum[w];    // fixed order: deterministic
        g_part[blockIdx.x] = s;
        __threadfence();
        s_last = (atomicAdd(&g_done, 1) == 511);
    }
    __syncthreads();
    if (s_last && threadIdx.x < 32) {
        float s = 0.f;
        #pragma unroll
        for (int q = 0; q < 16; q++) s += g_part[q * 32 + threadIdx.x];
        #pragma unroll
        for (int o = 16; o > 0; o >>= 1) s += __shfl_xor_sync(0xffffffffu, s, o);
        if (threadIdx.x == 0) out[0] = s / (float)NROW;
    }
}

// ---------------------------------------------------------------------------
extern "C" void kernel_launch(void* const* d_in, const int* in_sizes, int n_in,
                              void* d_out, int out_size) {
    const float* X = (const float*)d_in[0];
    const int* lab = (const int*)d_in[1];
    float* out = (float*)d_out;

    cudaFuncSetAttribute(dist_kernel, cudaFuncAttributeMaxDynamicSharedMemorySize, SMEM_TOTAL);

    prep_kernel<<<NROW / 8 + 64, 256>>>(X, lab);
    dist_kernel<<<528, 256, SMEM_TOTAL>>>(lab);
    hneg_kernel<<<NROW / 8, 256>>>(lab, out);
}